// round 16
// baseline (speedup 1.0000x reference)
#include <cuda_runtime.h>

// CRF forward + Viterbi, role-split warp groups with FINE thread splits.
// One CTA per batch, 288 threads:
//   threads 0-95   (warps 0-2): forward, 2 threads/state (24 prev each),
//                               shfl_xor(1) merge of partial dots.
//   threads 96-287 (warps 3-8): viterbi, 4 threads/state (12 prev each),
//                               shfl_xor(1)+shfl_xor(2) index-aware merge.
// Independent named barriers per group; lagged scalar normalizer;
// double-buffered publish => ONE barrier per step per group.
//
// Output layout (float32): [logz(B) | scores(B) | paths(B*T)]

#define Bc 512
#define Tc 1024
#define Kc 48
#define START_T 46
#define END_T 47
#define NEGV (-10000.0f)

#define OFF_BP    0                         // [T][48] uint8 = 49152
#define OFF_W     (Tc*Kc)                   // [2][48] float = 384
#define OFF_V     (OFF_W + 2*Kc*4)          // 384
#define OFF_RED   (OFF_V + 2*Kc*4)          // 2 floats (+pad)
#define OFF_AFIN  (OFF_RED + 16)            // 192
#define OFF_VFIN  (OFF_AFIN + Kc*4)         // 192
#define OFF_MC    (OFF_VFIN + Kc*4)         // 64*48 = 3072
#define OFF_EC    (OFF_MC + 64*Kc)          // 64
#define OFF_LAST  (OFF_EC + 64)             // 4
#define SMEM_TOTAL (OFF_LAST + 16)          // ~53.5 KB

typedef unsigned long long u64;

__device__ __forceinline__ float ninf() { return __int_as_float(0xff800000); }
__device__ __forceinline__ u64 pk2(float lo, float hi) {
    u64 r; asm("mov.b64 %0,{%1,%2};" : "=l"(r) : "f"(lo), "f"(hi)); return r;
}
__device__ __forceinline__ void upk2(u64 x, float& lo, float& hi) {
    asm("mov.b64 {%0,%1},%2;" : "=f"(lo), "=f"(hi) : "l"(x));
}
__device__ __forceinline__ u64 fma2(u64 a, u64 b, u64 c) {
    u64 d; asm("fma.rn.f32x2 %0,%1,%2,%3;" : "=l"(d) : "l"(a), "l"(b), "l"(c)); return d;
}
__device__ __forceinline__ u64 add2(u64 a, u64 b) {
    u64 d; asm("add.rn.f32x2 %0,%1,%2;" : "=l"(d) : "l"(a), "l"(b)); return d;
}

__global__ void __launch_bounds__(288, 4)
crf_fused_kernel(const float* __restrict__ feats,
                 const float* __restrict__ trans,
                 float* __restrict__ out)
{
    extern __shared__ unsigned char smem[];
    unsigned char* bptr = smem + OFF_BP;
    float* wp    = (float*)(smem + OFF_W);     // [buf][48] exp-weights
    float* vp    = (float*)(smem + OFF_V);     // [buf][48] viterbi values
    float* red   = (float*)(smem + OFF_RED);   // [buf] alpha[state 0]
    float* a_fin = (float*)(smem + OFF_AFIN);
    float* v_fin = (float*)(smem + OFF_VFIN);
    unsigned char* Mc = smem + OFF_MC;
    unsigned char* Ec = smem + OFF_EC;
    int* lastp = (int*)(smem + OFF_LAST);

    const int b   = blockIdx.x;
    const int tid = threadIdx.x;

    if (tid < 2) red[tid] = 0.f;
    __syncthreads();

    if (tid < 96) {
        // ============ FORWARD group (warps 0-2): 2 threads/state ============
        const int lane = tid & 31;
        const int wz   = tid >> 5;
        const int s    = wz * 16 + (lane >> 1);
        const int h    = lane & 1;
        const int pbase = h * 24;

        u64 E2[12];                               // exp(masked trans slice)
#pragma unroll
        for (int j = 0; j < 12; j++) {
            int p0 = pbase + 2 * j, p1 = p0 + 1;
            float t0 = trans[s * Kc + p0];
            float t1 = trans[s * Kc + p1];
            if (s == START_T) { t0 = NEGV; t1 = NEGV; }
            if (p0 == END_T) t0 = NEGV;
            if (p1 == END_T) t1 = NEGV;
            E2[j] = pk2(__expf(t0), __expf(t1));  // exp(-10000) == 0 exactly
        }

        float al = (s == START_T) ? 0.f : NEGV;
        float mc = 0.f;
        const float* fbp = feats + (size_t)b * Tc * Kc + s;
        float fA = fbp[0], fB = fbp[Kc];

        for (int t = 0; t < Tc; t++) {
            const int buf = t & 1;
            if (h == 0) wp[buf * Kc + s] = __expf(al - mc);  // -inf -> 0 (safe)
            const int tp = (t + 2 < Tc) ? (t + 2) : t;
            float fC = fbp[tp * Kc];

            asm volatile("bar.sync 1, 96;" ::: "memory");
            float mn = red[1 - buf];

            const ulonglong2* w4 = (const ulonglong2*)(wp + buf * Kc) + h * 6;
            u64 P = 0ull, Q = 0ull;
#pragma unroll
            for (int j = 0; j < 6; j++) {
                ulonglong2 q = w4[j];
                P = fma2(q.x, E2[2 * j],     P);
                Q = fma2(q.y, E2[2 * j + 1], Q);
            }
            float x0, x1, x2, x3;
            upk2(P, x0, x1);
            upk2(Q, x2, x3);
            float S = (x0 + x1) + (x2 + x3);
            S += __shfl_xor_sync(0xffffffffu, S, 1);
            al = mc + __logf(S) + fA;             // log(0)->-inf only START row
            if (h == 0 && s == 0) red[buf] = al;
            mc = mn; fA = fB; fB = fC;
        }
        if (h == 0) a_fin[s] = al;
    } else {
        // ============ VITERBI group (warps 3-8): 4 threads/state ============
        const int r    = tid - 96;
        const int lane = r & 31;
        const int wz   = r >> 5;
        const int s    = wz * 8 + (lane >> 2);
        const int q    = lane & 3;
        const int pbase = q * 12;

        u64 TR2[6];                               // masked trans slice
#pragma unroll
        for (int j = 0; j < 6; j++) {
            int p0 = pbase + 2 * j, p1 = p0 + 1;
            float t0 = trans[s * Kc + p0];
            float t1 = trans[s * Kc + p1];
            if (s == START_T) { t0 = NEGV; t1 = NEGV; }
            if (p0 == END_T) t0 = NEGV;
            if (p1 == END_T) t1 = NEGV;
            TR2[j] = pk2(t0, t1);
        }

        float v = (s == START_T) ? 0.f : NEGV;
        const float* fbp = feats + (size_t)b * Tc * Kc + s;
        float fA = fbp[0], fB = fbp[Kc];

        for (int t = 0; t < Tc; t++) {
            const int buf = t & 1;
            if (q == 0) vp[buf * Kc + s] = v;
            const int tp = (t + 2 < Tc) ? (t + 2) : t;
            float fC = fbp[tp * Kc];

            asm volatile("bar.sync 2, 192;" ::: "memory");

            const ulonglong2* v4 = (const ulonglong2*)(vp + buf * Kc) + 3 * q;
            float b0 = ninf(), b1 = ninf(), b2 = ninf();
            int   i0 = 0, i1 = 0, i2 = 0;
#pragma unroll
            for (int j = 0; j < 3; j++) {
                ulonglong2 qq = v4[j];
                u64 c01 = add2(qq.x, TR2[2 * j]);
                u64 c23 = add2(qq.y, TR2[2 * j + 1]);
                float s0, s1, s2, s3;
                upk2(c01, s0, s1);
                upk2(c23, s2, s3);
                if (j == 0) {       // local cands 0..3 (ascending => strict '>')
                    if (s0 > b0) { b0 = s0; i0 = 0; }
                    if (s1 > b0) { b0 = s1; i0 = 1; }
                    if (s2 > b0) { b0 = s2; i0 = 2; }
                    if (s3 > b0) { b0 = s3; i0 = 3; }
                } else if (j == 1) { // 4..7
                    if (s0 > b1) { b1 = s0; i1 = 4; }
                    if (s1 > b1) { b1 = s1; i1 = 5; }
                    if (s2 > b1) { b1 = s2; i1 = 6; }
                    if (s3 > b1) { b1 = s3; i1 = 7; }
                } else {            // 8..11
                    if (s0 > b2) { b2 = s0; i2 = 8; }
                    if (s1 > b2) { b2 = s1; i2 = 9; }
                    if (s2 > b2) { b2 = s2; i2 = 10; }
                    if (s3 > b2) { b2 = s3; i2 = 11; }
                }
            }
            float best = b0; int li = i0;
            if (b1 > best) { best = b1; li = i1; }
            if (b2 > best) { best = b2; li = i2; }
            int bi = pbase + li;

            // index-aware merges (first-occurrence ties)
#pragma unroll
            for (int o = 1; o <= 2; o <<= 1) {
                float ob = __shfl_xor_sync(0xffffffffu, best, o);
                int   oi = __shfl_xor_sync(0xffffffffu, bi, o);
                if (ob > best || (ob == best && oi < bi)) { best = ob; bi = oi; }
            }

            if (q == 0) {
                v = best + fA;
                bptr[t * Kc + s] = (unsigned char)bi;
            }
            fA = fB; fB = fC;
        }
        if (q == 0) v_fin[s] = v;
    }

    __syncthreads();

    // Termination: tid 0 -> logz ; tid 96 -> viterbi terminal (parallel warps)
    if (tid == 0) {
        float mx = ninf();
#pragma unroll
        for (int p = 0; p < Kc; p++) {
            float te = (p == END_T) ? NEGV : trans[END_T * Kc + p];
            mx = fmaxf(mx, a_fin[p] + te);
        }
        float sum = 0.f;
#pragma unroll
        for (int p = 0; p < Kc; p++) {
            float te = (p == END_T) ? NEGV : trans[END_T * Kc + p];
            sum += __expf((a_fin[p] + te) - mx);
        }
        out[b] = mx + __logf(sum);
    }
    if (tid == 96) {
        float bestT = ninf(); int last = 0;
#pragma unroll
        for (int p = 0; p < Kc; p++) {
            float te = (p == END_T) ? NEGV : trans[END_T * Kc + p];
            float tm = v_fin[p] + te;
            if (tm > bestT) { bestT = tm; last = p; }
        }
        out[Bc + b] = bestT;
        *lastp = last;
    }
    __syncthreads();

    // ---- Parallel backtrace: 64 chunks of 16 steps ----
    // Phase A: 384 tasks (chunk c, entry-group g of 8) -> Mc[c][e] exit tags.
    for (int ct = tid; ct < 384; ct += 288) {
        const int c = ct / 6;
        const int g = ct % 6;
        unsigned char tg[8];
#pragma unroll
        for (int e = 0; e < 8; e++) tg[e] = (unsigned char)(g * 8 + e);
        for (int i = 15; i >= 0; i--) {
            const unsigned char* row = bptr + (c * 16 + i) * Kc;
#pragma unroll
            for (int e = 0; e < 8; e++) tg[e] = row[tg[e]];
        }
#pragma unroll
        for (int e = 0; e < 8; e++) Mc[c * Kc + g * 8 + e] = tg[e];
    }
    __syncthreads();
    // Phase B: serial chain over 64 chunks
    if (tid == 0) {
        int tag = *lastp;
        for (int c = 63; c >= 0; c--) {
            Ec[c] = (unsigned char)tag;
            tag = Mc[c * Kc + tag];
        }
    }
    __syncthreads();
    // Phase C: emit 16 path entries per chunk
    if (tid < 64) {
        const int c = tid;
        float* pout = out + 2 * Bc + (size_t)b * Tc + c * 16;
        int tg = Ec[c];
        for (int i = 15; i >= 0; i--) {
            pout[i] = (float)tg;
            tg = bptr[(c * 16 + i) * Kc + tg];
        }
    }
}

extern "C" void kernel_launch(void* const* d_in, const int* in_sizes, int n_in,
                              void* d_out, int out_size)
{
    (void)in_sizes; (void)n_in; (void)out_size;
    const float* feats = (const float*)d_in[0];
    const float* trans = (const float*)d_in[1];
    float* out = (float*)d_out;

    cudaFuncSetAttribute(crf_fused_kernel,
                         cudaFuncAttributeMaxDynamicSharedMemorySize, SMEM_TOTAL);
    crf_fused_kernel<<<Bc, 288, SMEM_TOTAL>>>(feats, trans, out);
}